// round 16
// baseline (speedup 1.0000x reference)
#include <cuda_runtime.h>

#define NB 16
#define NS 256
#define NT 400
#define NMEL 80
#define NPRE 256
#define NENC 512
#define NH 1024
#define NATT 128
#define NFILT 32
#define KC 31
#define GRID 148
#define TPB 512
#define SMEM_BYTES 131072

struct Params {
    const float *memory, *dec_in, *Wpre1, *Wpre2, *Wih_a, *Whh_a, *bih_a, *bhh_a;
    const float *Wq, *Wm, *v, *Wc, *Wld, *Wih_d, *Whh_d, *bih_d, *bhh_d;
    const float *Wproj, *bproj, *Wgate, *bgate;
    const int* mlen;
    float *out_mel, *out_gate, *out_align;
};

__device__ float g_xs[NT * NB * NPRE];
__device__ float g_pm[NB * NS * NATT];
__device__ float g_ah[2][NB * NH];
__device__ float g_ac[NB * NH];
__device__ float g_dh[NB * NH];
__device__ float g_dc[NB * NH];
__device__ float g_aw[NB * NS];
__device__ float g_awc[NB * NS];
__device__ float g_ctx[NB * NENC];
__device__ float g_loc[NB * NS * NFILT];   // conv output [b][s][f]
__device__ float g_q[NB * NATT];           // query
__device__ float g_e[NB * NS];             // energies (masked)
__device__ unsigned g_flags[GRID];
__device__ unsigned g_gen = 0;

// Flag-based grid barrier: parallel arrival stores (no atomic serialization),
// block 0 aggregates with 147 polling threads, releases g_gen.
__device__ __forceinline__ void grid_sync() {
    __syncthreads();
    unsigned gen;
    asm volatile("ld.global.relaxed.gpu.u32 %0, [%1];" : "=r"(gen) : "l"(&g_gen) : "memory");
    if (blockIdx.x == 0) {
        const int tid = threadIdx.x;
        if (tid > 0 && tid < GRID) {
            unsigned v;
            do {
                asm volatile("ld.acquire.gpu.u32 %0, [%1];" : "=r"(v) : "l"(&g_flags[tid]) : "memory");
            } while (v != gen + 1);
        }
        __syncthreads();
        if (tid == 0)
            asm volatile("st.release.gpu.u32 [%0], %1;" :: "l"(&g_gen), "r"(gen + 1) : "memory");
    } else {
        if (threadIdx.x == 0) {
            asm volatile("st.release.gpu.u32 [%0], %1;" :: "l"(&g_flags[blockIdx.x]), "r"(gen + 1) : "memory");
            unsigned v;
            do {
                asm volatile("ld.acquire.gpu.u32 %0, [%1];" : "=r"(v) : "l"(&g_gen) : "memory");
            } while (v != gen + 1);
        }
        __syncthreads();
    }
}

__device__ __forceinline__ float sigf(float x) { return 1.0f / (1.0f + __expf(-x)); }

// fast tanh for energies only: exact at saturation, ~1e-6 rel in between
__device__ __forceinline__ float tanhf_fast(float x) {
    float e = __expf(2.0f * x);
    return 1.0f - 2.0f / (e + 1.0f);
}

__device__ __forceinline__ void wred16(float* a) {
#pragma unroll
    for (int off = 16; off > 0; off >>= 1)
#pragma unroll
        for (int i = 0; i < 16; ++i)
            a[i] += __shfl_xor_sync(0xffffffffu, a[i], off);
}

__device__ __forceinline__ float pick16(const float* a, int lane) {
    float v = a[0];
#pragma unroll
    for (int b = 1; b < 16; ++b)
        if (lane == b) v = a[b];
    return v;
}

__device__ __forceinline__ void wred32(float* a) {
#pragma unroll
    for (int off = 16; off > 0; off >>= 1)
#pragma unroll
        for (int i = 0; i < 32; ++i)
            a[i] += __shfl_xor_sync(0xffffffffu, a[i], off);
}

__device__ __forceinline__ float pick32(const float* a, int lane) {
    float v = a[0];
#pragma unroll
    for (int b = 1; b < 32; ++b)
        if (lane == b) v = a[b];
    return v;
}

__device__ __forceinline__ void wred8(float* a) {
#pragma unroll
    for (int off = 16; off > 0; off >>= 1)
#pragma unroll
        for (int i = 0; i < 8; ++i)
            a[i] += __shfl_xor_sync(0xffffffffu, a[i], off);
}

__device__ __forceinline__ float pick8(const float* a, int lane) {
    float v = a[0];
#pragma unroll
    for (int b = 1; b < 8; ++b)
        if (lane == b) v = a[b];
    return v;
}

// 4-gate-row x 8-batch GEMM accumulation over NCH chunks of 128 k's.
template <int XSTRIDE, int NCH>
__device__ __forceinline__ void gemm4_accum(
    const float4* __restrict__ W0, const float4* __restrict__ W1,
    const float4* __restrict__ W2, const float4* __restrict__ W3,
    const float* __restrict__ sXb, int lane, float* av)
{
    float4 c0 = W0[lane], c1 = W1[lane], c2 = W2[lane], c3 = W3[lane];
#pragma unroll
    for (int c = 0; c < NCH; ++c) {
        const int nidx = ((c + 1 < NCH) ? (c + 1) : c) * 32 + lane;
        float4 n0 = W0[nidx], n1 = W1[nidx], n2 = W2[nidx], n3 = W3[nidx];
        const float* xb = sXb + c * 128 + lane * 4;
        float4 xc = *(const float4*)(xb);
#pragma unroll
        for (int b = 0; b < 8; ++b) {
            float4 xn = (b < 7) ? *(const float4*)(xb + (b + 1) * XSTRIDE) : xc;
            av[b]      = fmaf(c0.x, xc.x, fmaf(c0.y, xc.y, fmaf(c0.z, xc.z, fmaf(c0.w, xc.w, av[b]))));
            av[8 + b]  = fmaf(c1.x, xc.x, fmaf(c1.y, xc.y, fmaf(c1.z, xc.z, fmaf(c1.w, xc.w, av[8 + b]))));
            av[16 + b] = fmaf(c2.x, xc.x, fmaf(c2.y, xc.y, fmaf(c2.z, xc.z, fmaf(c2.w, xc.w, av[16 + b]))));
            av[24 + b] = fmaf(c3.x, xc.x, fmaf(c3.y, xc.y, fmaf(c3.z, xc.z, fmaf(c3.w, xc.w, av[24 + b]))));
            xc = xn;
        }
        c0 = n0; c1 = n1; c2 = n2; c3 = n3;
    }
}

// mel/gate projection for timestep tq (blocks 128..133 effective)
__device__ void write_outputs(const Params& P, int tq) {
    const int w = threadIdx.x >> 5, lane = threadIdx.x & 31;
    int gw = ((int)blockIdx.x - 128) * 16 + w;   // 0..79 mel rows, 80 gate
    if (gw > 80) return;
    const float* wr = (gw < 80) ? (P.Wproj + gw * (NH + NENC)) : P.Wgate;
    float bias = (gw < 80) ? P.bproj[gw] : P.bgate[0];
    const float4* wr4 = (const float4*)wr;
    const float4* dh4 = (const float4*)g_dh;
    const float4* cx4 = (const float4*)g_ctx;
    float acc[16];
#pragma unroll
    for (int b = 0; b < 16; ++b) acc[b] = 0.f;
    for (int k = lane; k < NH / 4; k += 32) {
        float4 wv = wr4[k];
#pragma unroll
        for (int b = 0; b < 16; ++b) {
            float4 x = __ldcg(dh4 + b * 256 + k);
            acc[b] = fmaf(wv.x, x.x, fmaf(wv.y, x.y, fmaf(wv.z, x.z, fmaf(wv.w, x.w, acc[b]))));
        }
    }
    for (int k = lane; k < NENC / 4; k += 32) {
        float4 wv = wr4[256 + k];
#pragma unroll
        for (int b = 0; b < 16; ++b) {
            float4 x = __ldcg(cx4 + b * 128 + k);
            acc[b] = fmaf(wv.x, x.x, fmaf(wv.y, x.y, fmaf(wv.z, x.z, fmaf(wv.w, x.w, acc[b]))));
        }
    }
    wred16(acc);
    if (lane < 16) {
        float val = pick16(acc, lane) + bias;
        if (gw < 80) P.out_mel[(lane * NMEL + gw) * NT + tq] = val;
        else         P.out_gate[lane * NT + tq] = val;
    }
}

__global__ void __launch_bounds__(TPB) decoder_kernel(Params P) {
    extern __shared__ float smf[];
    const int blk = blockIdx.x, tid = threadIdx.x;
    const int w = tid >> 5, lane = tid & 31;
    const int h = tid >> 8, lt = tid & 255;

    // ---------- prelude: zero state ----------
    {
        const int g0 = blk * TPB + tid, gs = GRID * TPB;
        for (int i = g0; i < NB * NH; i += gs) {
            g_ah[0][i] = 0.f; g_ah[1][i] = 0.f;
            g_ac[i] = 0.f; g_dh[i] = 0.f; g_dc[i] = 0.f;
        }
        for (int i = g0; i < NB * NS; i += gs) { g_aw[i] = 0.f; g_awc[i] = 0.f; }
        for (int i = g0; i < NB * NENC; i += gs) g_ctx[i] = 0.f;
        for (int i = g0; i < NB * NPRE; i += gs) g_xs[i] = 0.f;
    }
    // prenet for t=1..399
    {
        float* sx = smf + h * 96;
        float* sh1 = smf + 192 + h * 256;
        const int NP = (NT - 1) * NB;
        const int KMAX = (NP + 2 * GRID - 1) / (2 * GRID);
        for (int k = 0; k < KMAX; ++k) {
            int pi = blk * 2 + h + k * 2 * GRID;
            bool act = pi < NP;
            int tt = act ? pi / NB + 1 : 1, b = act ? pi % NB : 0;
            if (act && lt < NMEL) sx[lt] = P.dec_in[(b * NMEL + lt) * NT + (tt - 1)];
            __syncthreads();
            float a1v = 0.f;
            if (act) {
                const float* w1 = P.Wpre1 + lt * NMEL;
#pragma unroll 4
                for (int kk = 0; kk < NMEL; ++kk) a1v += w1[kk] * sx[kk];
                sh1[lt] = fmaxf(a1v, 0.f);
            }
            __syncthreads();
            if (act) {
                const float4* w2 = (const float4*)(P.Wpre2 + lt * NPRE);
                const float4* h4 = (const float4*)sh1;
                float a = 0.f;
#pragma unroll 8
                for (int kk = 0; kk < NPRE / 4; ++kk) {
                    float4 wv = w2[kk], x = h4[kk];
                    a = fmaf(wv.x, x.x, fmaf(wv.y, x.y, fmaf(wv.z, x.z, fmaf(wv.w, x.w, a))));
                }
                g_xs[(tt * NB + b) * NPRE + lt] = fmaxf(a, 0.f);
            }
            __syncthreads();
        }
    }
    // processed memory pm[b][s][a]
    {
        float* srow = smf + h * 512;
        const int NR = NB * NS;
        const int RMAX = (NR + 2 * GRID - 1) / (2 * GRID);
        const int wl = w & 7;
        for (int k = 0; k < RMAX; ++k) {
            int r = blk * 2 + h + k * 2 * GRID;
            bool act = r < NR;
            __syncthreads();
            if (act) for (int i = lt; i < NENC; i += 256) srow[i] = P.memory[(size_t)r * NENC + i];
            __syncthreads();
            if (act) {
                const float4* sr4 = (const float4*)srow;
                for (int a = wl; a < NATT; a += 8) {
                    const float4* wm = (const float4*)(P.Wm + a * NENC);
                    float acc = 0.f;
#pragma unroll
                    for (int kk = lane; kk < NENC / 4; kk += 32) {
                        float4 wv = wm[kk], x = sr4[kk];
                        acc = fmaf(wv.x, x.x, fmaf(wv.y, x.y, fmaf(wv.z, x.z, fmaf(wv.w, x.w, acc))));
                    }
#pragma unroll
                    for (int off = 16; off > 0; off >>= 1)
                        acc += __shfl_xor_sync(0xffffffffu, acc, off);
                    if (lane == 0) g_pm[(size_t)r * NATT + a] = acc;
                }
            }
        }
    }
    grid_sync();

    int p = 0;

    for (int t = 0; t < NT; ++t) {
        float Dv[32];  // decoder accs, live P2a -> P3

        // ===== PHASE 1: attention LSTM | outputs(t-1) | conv -> g_loc =====
        if (blk < 128) {
            float* sA = smf;                        // [16][768]
            float* sH = smf + NB * 768;             // [16][1024]
            float* zb = smf + NB * 768 + NB * NH;   // [4][8][16]
            {
                float4* sA4 = (float4*)sA;
                const float4* xs4 = (const float4*)(g_xs + (size_t)t * NB * NPRE);
                for (int i = tid; i < NB * NPRE / 4; i += TPB)
                    sA4[(i >> 6) * 192 + (i & 63)] = __ldcg(xs4 + i);
                const float4* cx4 = (const float4*)g_ctx;
                for (int i = tid; i < NB * NENC / 4; i += TPB)
                    sA4[(i >> 7) * 192 + 64 + (i & 127)] = __ldcg(cx4 + i);
                float4* sH4 = (float4*)sH;
                const float4* ah4 = (const float4*)g_ah[p];
                for (int i = tid; i < NB * NH / 4; i += TPB) sH4[i] = __ldcg(ah4 + i);
            }
            __syncthreads();

            const int ul = w >> 1, bh = w & 1;
            const int u = blk * 8 + ul;
            float av[32];
#pragma unroll
            for (int i = 0; i < 32; ++i) av[i] = 0.f;
            gemm4_accum<768, 6>((const float4*)(P.Wih_a + (size_t)u * 768),
                                (const float4*)(P.Wih_a + (size_t)(NH + u) * 768),
                                (const float4*)(P.Wih_a + (size_t)(2 * NH + u) * 768),
                                (const float4*)(P.Wih_a + (size_t)(3 * NH + u) * 768),
                                sA + bh * 8 * 768, lane, av);
            gemm4_accum<NH, 8>((const float4*)(P.Whh_a + (size_t)u * NH),
                               (const float4*)(P.Whh_a + (size_t)(NH + u) * NH),
                               (const float4*)(P.Whh_a + (size_t)(2 * NH + u) * NH),
                               (const float4*)(P.Whh_a + (size_t)(3 * NH + u) * NH),
                               sH + bh * 8 * NH, lane, av);
            wred32(av);
            {
                float val = pick32(av, lane);
                zb[(lane >> 3) * 128 + ul * 16 + bh * 8 + (lane & 7)] = val;
            }
            __syncthreads();
            if (tid < 128) {
                const int ul2 = tid >> 4, b = tid & 15;
                const int uu = blk * 8 + ul2;
                float zi = zb[ul2 * 16 + b]          + P.bih_a[uu]          + P.bhh_a[uu];
                float zf = zb[128 + ul2 * 16 + b]    + P.bih_a[NH + uu]     + P.bhh_a[NH + uu];
                float zg = zb[256 + ul2 * 16 + b]    + P.bih_a[2 * NH + uu] + P.bhh_a[2 * NH + uu];
                float zo = zb[384 + ul2 * 16 + b]    + P.bih_a[3 * NH + uu] + P.bhh_a[3 * NH + uu];
                float c = sigf(zf) * g_ac[b * NH + uu] + sigf(zi) * tanhf(zg);
                g_ac[b * NH + uu] = c;
                g_ah[p ^ 1][b * NH + uu] = sigf(zo) * tanhf(c);
            }
        } else if (blk < 134) {
            if (t > 0) write_outputs(P, t - 1);
        } else {
            // location conv for step t (reads aw/awc of t-1) -> g_loc
            float* s_wcT = smf;  // [kk][ch][f] 1984
            for (int i = tid; i < NFILT * 2 * KC; i += TPB) {
                int f = i / (2 * KC), r = i % (2 * KC), ch = r / KC, kk = r % KC;
                s_wcT[(kk * 2 + ch) * 32 + f] = P.Wc[i];
            }
            __syncthreads();
            const int id0 = (blk - 134) * 16 + w;   // 0..223
#pragma unroll 1
            for (int id = id0; id < 256; id += 224) {
                const int b = id >> 4, sb = (id & 15) * 16;
                const float* awb = g_aw + b * NS;
                const float* awcb = g_awc + b * NS;
                float acc[16];
#pragma unroll
                for (int j = 0; j < 16; ++j) acc[j] = 0.f;
                float ring[16];
#pragma unroll
                for (int j = 0; j < 16; ++j) {
                    int s = sb + j - 15;
                    ring[j] = (s >= 0) ? __ldcg(awb + s) : 0.f;
                }
#pragma unroll
                for (int k = 0; k < KC; ++k) {
                    float wk = s_wcT[(k * 2 + 0) * 32 + lane];
#pragma unroll
                    for (int j = 0; j < 16; ++j)
                        acc[j] = fmaf(wk, ring[(k + j) & 15], acc[j]);
                    int s = sb + k + 1;
                    ring[k & 15] = (s < NS) ? __ldcg(awb + s) : 0.f;
                }
#pragma unroll
                for (int j = 0; j < 16; ++j) {
                    int s = sb + j - 15;
                    ring[j] = (s >= 0) ? __ldcg(awcb + s) : 0.f;
                }
#pragma unroll
                for (int k = 0; k < KC; ++k) {
                    float wk = s_wcT[(k * 2 + 1) * 32 + lane];
#pragma unroll
                    for (int j = 0; j < 16; ++j)
                        acc[j] = fmaf(wk, ring[(k + j) & 15], acc[j]);
                    int s = sb + k + 1;
                    ring[k & 15] = (s < NS) ? __ldcg(awcb + s) : 0.f;
                }
#pragma unroll
                for (int j = 0; j < 16; ++j)
                    g_loc[((size_t)b * NS + sb + j) * NFILT + lane] = acc[j];
            }
        }
        grid_sync();
        p ^= 1;  // g_ah[p] = new ah

        // ===== PHASE 2a: q (16 blocks) | decoder Wih_d ah-part =====
        if (blk < 16) {
            const int b = blk;
            float* s_ah = smf;  // 1024
            if (tid < 256) ((float4*)s_ah)[tid] = __ldcg((const float4*)(g_ah[p] + b * NH) + tid);
            __syncthreads();
            const float4* ah4 = (const float4*)s_ah;
            for (int a = w * 8; a < w * 8 + 8; ++a) {
                const float4* wq = (const float4*)(P.Wq + (size_t)a * NH);
                float acc = 0.f;
#pragma unroll
                for (int k = lane; k < NH / 4; k += 32) {
                    float4 wv = wq[k], x = ah4[k];
                    acc = fmaf(wv.x, x.x, fmaf(wv.y, x.y, fmaf(wv.z, x.z, fmaf(wv.w, x.w, acc))));
                }
#pragma unroll
                for (int off = 16; off > 0; off >>= 1)
                    acc += __shfl_xor_sync(0xffffffffu, acc, off);
                if (lane == 0) g_q[b * NATT + a] = acc;
            }
        } else if (blk < 144) {
            float* sAh = smf;  // [16][1024]
            {
                float4* a4 = (float4*)sAh;
                const float4* ga4 = (const float4*)g_ah[p];
                for (int i = tid; i < NB * NH / 4; i += TPB) a4[i] = __ldcg(ga4 + i);
            }
            __syncthreads();
            const int ul = w >> 1, bh = w & 1;
            const int u = (blk - 16) * 8 + ul;
#pragma unroll
            for (int i = 0; i < 32; ++i) Dv[i] = 0.f;
            gemm4_accum<NH, 8>((const float4*)(P.Wih_d + (size_t)u * 1536),
                               (const float4*)(P.Wih_d + (size_t)(NH + u) * 1536),
                               (const float4*)(P.Wih_d + (size_t)(2 * NH + u) * 1536),
                               (const float4*)(P.Wih_d + (size_t)(3 * NH + u) * 1536),
                               sAh + bh * 8 * NH, lane, Dv);
        }
        grid_sync();

        // ===== PHASE 2b: distributed energies (blocks 0..15 + 144..147) =====
        {
            int r = (blk < 16) ? blk : ((blk >= 144) ? 16 + (blk - 144) : -1);
            if (r >= 0) {
                float* s_wldT2 = smf + 16384;            // [f][a] 4096
                float* s_locw = smf + 20480 + w * 256;   // per-warp 8x32
                for (int i = tid; i < NATT * NFILT; i += TPB)
                    s_wldT2[(i & 31) * NATT + (i >> 5)] = P.Wld[i];
                __syncthreads();
#pragma unroll 1
                for (int id = r * 16 + w; id < 512; id += 320) {
                    const int b = id >> 5, sb = (id & 31) * 8;
                    const float4* gl4 = (const float4*)(g_loc + ((size_t)b * NS + sb) * NFILT);
                    ((float4*)s_locw)[lane] = __ldcg(gl4 + lane);
                    ((float4*)s_locw)[32 + lane] = __ldcg(gl4 + 32 + lane);
                    __syncwarp();
                    float q0 = __ldcg(&g_q[b * NATT + lane]);
                    float q1 = __ldcg(&g_q[b * NATT + lane + 32]);
                    float q2 = __ldcg(&g_q[b * NATT + lane + 64]);
                    float q3 = __ldcg(&g_q[b * NATT + lane + 96]);
                    const float* pmb = g_pm + ((size_t)b * NS + sb) * NATT;
                    float a0[8], a1[8], a2[8], a3[8];
#pragma unroll
                    for (int j = 0; j < 8; ++j) {
                        const float* pr = pmb + j * NATT;
                        a0[j] = q0 + pr[lane];
                        a1[j] = q1 + pr[lane + 32];
                        a2[j] = q2 + pr[lane + 64];
                        a3[j] = q3 + pr[lane + 96];
                    }
#pragma unroll 4
                    for (int f = 0; f < NFILT; ++f) {
                        float w0 = s_wldT2[f * NATT + lane];
                        float w1 = s_wldT2[f * NATT + lane + 32];
                        float w2 = s_wldT2[f * NATT + lane + 64];
                        float w3 = s_wldT2[f * NATT + lane + 96];
#pragma unroll
                        for (int j = 0; j < 8; ++j) {
                            float lv = s_locw[j * 32 + f];
                            a0[j] = fmaf(w0, lv, a0[j]);
                            a1[j] = fmaf(w1, lv, a1[j]);
                            a2[j] = fmaf(w2, lv, a2[j]);
                            a3[j] = fmaf(w3, lv, a3[j]);
                        }
                    }
                    float v0 = P.v[lane], v1 = P.v[lane + 32], v2 = P.v[lane + 64], v3 = P.v[lane + 96];
                    float es[8];
#pragma unroll
                    for (int j = 0; j < 8; ++j)
                        es[j] = v0 * tanhf_fast(a0[j]) + v1 * tanhf_fast(a1[j])
                              + v2 * tanhf_fast(a2[j]) + v3 * tanhf_fast(a3[j]);
                    wred8(es);
                    const int ml = P.mlen[b];
                    if (lane < 8) {
                        int s = sb + lane;
                        g_e[b * NS + s] = (s < ml) ? pick8(es, lane) : -1e9f;
                    }
                    __syncwarp();
                }
            }
        }
        grid_sync();

        // ===== PHASE 2c: softmax + ctx (16 blocks) | decoder Whh_d dh-part =====
        if (blk < 16) {
            const int b = blk;
            float* s_aw = smf;        // 256
            float* s_red = smf + 256; // 32
            float val = 0.f, ex = 0.f;
            if (tid < 256) {
                val = __ldcg(&g_e[b * NS + tid]);
                float m = val;
#pragma unroll
                for (int off = 16; off > 0; off >>= 1)
                    m = fmaxf(m, __shfl_xor_sync(0xffffffffu, m, off));
                if (lane == 0) s_red[w] = m;
            }
            __syncthreads();
            if (tid == 0) {
                float mm = s_red[0];
                for (int i = 1; i < 8; ++i) mm = fmaxf(mm, s_red[i]);
                s_red[8] = mm;
            }
            __syncthreads();
            if (tid < 256) {
                ex = expf(val - s_red[8]);
                float sv = ex;
#pragma unroll
                for (int off = 16; off > 0; off >>= 1)
                    sv += __shfl_xor_sync(0xffffffffu, sv, off);
                if (lane == 0) s_red[16 + w] = sv;
            }
            __syncthreads();
            if (tid == 0) {
                float ss = 0.f;
                for (int i = 0; i < 8; ++i) ss += s_red[16 + i];
                s_red[24] = ss;
            }
            __syncthreads();
            if (tid < 256) {
                float awn = ex / s_red[24];
                s_aw[tid] = awn;
                g_aw[b * NS + tid] = awn;
                float awc_old = __ldcg(&g_awc[b * NS + tid]);
                g_awc[b * NS + tid] = awc_old + awn;
                P.out_align[((size_t)b * NT + t) * NS + tid] = awn;
            }
            __syncthreads();
            {
                const float* mem_b = P.memory + (size_t)b * NS * NENC;
                float a0 = 0.f;
#pragma unroll 8
                for (int s = 0; s < NS; ++s)
                    a0 = fmaf(s_aw[s], mem_b[s * NENC + tid], a0);
                g_ctx[b * NENC + tid] = a0;
            }
        } else if (blk < 144) {
            float* sDh = smf;  // [16][1024]
            {
                float4* d4 = (float4*)sDh;
                const float4* gd4 = (const float4*)g_dh;
                for (int i = tid; i < NB * NH / 4; i += TPB) d4[i] = __ldcg(gd4 + i);
            }
            __syncthreads();
            const int ul = w >> 1, bh = w & 1;
            const int u = (blk - 16) * 8 + ul;
            gemm4_accum<NH, 8>((const float4*)(P.Whh_d + (size_t)u * NH),
                               (const float4*)(P.Whh_d + (size_t)(NH + u) * NH),
                               (const float4*)(P.Whh_d + (size_t)(2 * NH + u) * NH),
                               (const float4*)(P.Whh_d + (size_t)(3 * NH + u) * NH),
                               sDh + bh * 8 * NH, lane, Dv);
        }
        grid_sync();

        // ===== PHASE 3: decoder ctx-part + cell finish =====
        if (blk >= 16 && blk < 144) {
            float* sC = smf;               // [16][512]
            float* zb = smf + NB * NENC;   // [4][8][16]
            {
                float4* c4 = (float4*)sC;
                const float4* gc4 = (const float4*)g_ctx;
                for (int i = tid; i < NB * NENC / 4; i += TPB) c4[i] = __ldcg(gc4 + i);
            }
            __syncthreads();
            const int ul = w >> 1, bh = w & 1;
            const int u = (blk - 16) * 8 + ul;
            gemm4_accum<NENC, 4>((const float4*)(P.Wih_d + (size_t)u * 1536 + NH),
                                 (const float4*)(P.Wih_d + (size_t)(NH + u) * 1536 + NH),
                                 (const float4*)(P.Wih_d + (size_t)(2 * NH + u) * 1536 + NH),
                                 (const float4*)(P.Wih_d + (size_t)(3 * NH + u) * 1536 + NH),
                                 sC + bh * 8 * NENC, lane, Dv);
            wred32(Dv);
            {
                float val = pick32(Dv, lane);
                zb[(lane >> 3) * 128 + ul * 16 + bh * 8 + (lane & 7)] = val;
            }
            __syncthreads();
            if (tid < 128) {
                const int ul2 = tid >> 4, b = tid & 15;
                const int uu = (blk - 16) * 8 + ul2;
                float zi = zb[ul2 * 16 + b]       + P.bih_d[uu]          + P.bhh_d[uu];
                float zf = zb[128 + ul2 * 16 + b] + P.bih_d[NH + uu]     + P.bhh_d[NH + uu];
                float zg = zb[256 + ul2 * 16 + b] + P.bih_d[2 * NH + uu] + P.bhh_d[2 * NH + uu];
                float zo = zb[384 + ul2 * 16 + b] + P.bih_d[3 * NH + uu] + P.bhh_d[3 * NH + uu];
                float c = sigf(zf) * g_dc[b * NH + uu] + sigf(zi) * tanhf(zg);
                g_dc[b * NH + uu] = c;
                g_dh[b * NH + uu] = sigf(zo) * tanhf(c);
            }
        }
        grid_sync();
    }

    // final timestep outputs
    if (blk >= 128 && blk < 134) write_outputs(P, NT - 1);
}

extern "C" void kernel_launch(void* const* d_in, const int* in_sizes, int n_in,
                              void* d_out, int out_size) {
    Params P;
    P.memory = (const float*)d_in[0];
    P.dec_in = (const float*)d_in[1];
    P.Wpre1  = (const float*)d_in[2];
    P.Wpre2  = (const float*)d_in[3];
    P.Wih_a  = (const float*)d_in[4];
    P.Whh_a  = (const float*)d_in[5];
    P.bih_a  = (const float*)d_in[6];
    P.bhh_a  = (const float*)d_in[7];
    P.Wq     = (const float*)d_in[8];
    P.Wm     = (const float*)d_in[9];
    P.v      = (const float*)d_in[10];
    P.Wc     = (const float*)d_in[11];
    P.Wld    = (const float*)d_in[12];
    P.Wih_d  = (const float*)d_in[13];
    P.Whh_d  = (const float*)d_in[14];
    P.bih_d  = (const float*)d_in[15];
    P.bhh_d  = (const float*)d_in[16];
    P.Wproj  = (const float*)d_in[17];
    P.bproj  = (const float*)d_in[18];
    P.Wgate  = (const float*)d_in[19];
    P.bgate  = (const float*)d_in[20];
    P.mlen   = (const int*)d_in[21];
    float* out = (float*)d_out;
    P.out_mel   = out;
    P.out_gate  = out + NB * NMEL * NT;
    P.out_align = out + NB * NMEL * NT + NB * NT;

    cudaFuncSetAttribute(decoder_kernel, cudaFuncAttributeMaxDynamicSharedMemorySize, SMEM_BYTES);
    decoder_kernel<<<GRID, TPB, SMEM_BYTES>>>(P);
}